// round 2
// baseline (speedup 1.0000x reference)
#include <cuda_runtime.h>

#define D_MODEL 1024
#define NHEAD   16
#define DKH     64
#define BATCH   2
#define SEQ     2048
#define MROWS   (BATCH*SEQ)   /* 4096 */

// ---------------- scratch (static device globals; no allocations) ----------
__device__ float g_q[(size_t)MROWS * D_MODEL];
__device__ float g_k[(size_t)MROWS * D_MODEL];
__device__ float g_v[(size_t)MROWS * D_MODEL];
__device__ float g_o[(size_t)MROWS * D_MODEL];

// ============================================================================
// SGEMM: C[M,N] = A[M,K] @ W[K,N] + bias[N]
// M=4096, N=K=1024 hardcoded. BM=BN=128, BK=8, TM=TN=8, 256 threads.
// dst: 0->g_q, 1->g_k, 2->g_v, 3->Cparam.  src_go: A from g_o instead of Aparam.
// ============================================================================
__global__ __launch_bounds__(256) void sgemm_bias_kernel(
    const float* __restrict__ Aparam, const float* __restrict__ W,
    const float* __restrict__ bias, float* __restrict__ Cparam,
    int dst, int src_go)
{
    const int N = D_MODEL, K = D_MODEL;
    __shared__ float As[8][128];   // transposed A tile: As[k][m]
    __shared__ float Bs[8][128];   // Bs[k][n]

    const float* A = src_go ? g_o : Aparam;
    float* C;
    switch (dst) {
        case 0:  C = g_q; break;
        case 1:  C = g_k; break;
        case 2:  C = g_v; break;
        default: C = Cparam; break;
    }

    const int tid  = threadIdx.x;
    const int bx   = blockIdx.x;   // N tile
    const int by   = blockIdx.y;   // M tile
    const int arow = tid >> 1;             // 0..127
    const int acol = (tid & 1) * 4;        // 0 or 4
    const int brow = tid >> 5;             // 0..7
    const int bcol = (tid & 31) * 4;       // 0..124
    const int tx   = tid & 15;
    const int ty   = tid >> 4;

    const float* Ap = A + (size_t)(by * 128 + arow) * K + acol;
    const float* Wp = W + (size_t)brow * N + bx * 128 + bcol;

    float acc[8][8];
#pragma unroll
    for (int i = 0; i < 8; i++)
#pragma unroll
        for (int j = 0; j < 8; j++) acc[i][j] = 0.f;

    for (int k0 = 0; k0 < K; k0 += 8) {
        float4 av = *(const float4*)(Ap + k0);
        As[acol + 0][arow] = av.x;
        As[acol + 1][arow] = av.y;
        As[acol + 2][arow] = av.z;
        As[acol + 3][arow] = av.w;
        *(float4*)&Bs[brow][bcol] = *(const float4*)(Wp + (size_t)k0 * N);
        __syncthreads();
#pragma unroll
        for (int k = 0; k < 8; k++) {
            float ar[8], br[8];
            *(float4*)&ar[0] = *(const float4*)&As[k][ty * 8];
            *(float4*)&ar[4] = *(const float4*)&As[k][ty * 8 + 4];
            *(float4*)&br[0] = *(const float4*)&Bs[k][tx * 8];
            *(float4*)&br[4] = *(const float4*)&Bs[k][tx * 8 + 4];
#pragma unroll
            for (int i = 0; i < 8; i++)
#pragma unroll
                for (int j = 0; j < 8; j++) acc[i][j] += ar[i] * br[j];
        }
        __syncthreads();
    }

    const int crow = by * 128 + ty * 8;
    const int ccol = bx * 128 + tx * 8;
    float4 bb0 = *(const float4*)&bias[ccol];
    float4 bb1 = *(const float4*)&bias[ccol + 4];
#pragma unroll
    for (int i = 0; i < 8; i++) {
        float4 v0, v1;
        v0.x = acc[i][0] + bb0.x; v0.y = acc[i][1] + bb0.y;
        v0.z = acc[i][2] + bb0.z; v0.w = acc[i][3] + bb0.w;
        v1.x = acc[i][4] + bb1.x; v1.y = acc[i][5] + bb1.y;
        v1.z = acc[i][6] + bb1.z; v1.w = acc[i][7] + bb1.w;
        float* Cp = C + (size_t)(crow + i) * N + ccol;
        *(float4*)Cp       = v0;
        *(float4*)(Cp + 4) = v1;
    }
}

// ============================================================================
// Flash attention, fp32, reads g_q/g_k/g_v, writes g_o.
// One block per (head-batch hb, 64-row Q tile).
// Q/K transposed in smem ([d][row], pad 68) so QK^T fragments are LDS.128.
// P stored transposed ([kcol][qrow]) so PV fragments are LDS.128.
// 256 threads as 16x16, 4x4 per thread. Online softmax.
// ============================================================================
#define BQ   64
#define BKT  64
#define SPAD 68     // row stride (floats); 68*4=272 bytes, 16B aligned

__global__ __launch_bounds__(256) void attn_kernel()
{
    extern __shared__ float sm[];
    float* Qt  = sm;                    // [64][SPAD]  Qt[d][r] (pre-scaled)
    float* Kt  = Qt  + 64 * SPAD;       // [64][SPAD]  Kt[d][c]
    float* Vs  = Kt  + 64 * SPAD;       // [64][SPAD]  Vs[c][d]
    float* Pt  = Vs  + 64 * SPAD;       // [64][SPAD]  Pt[c][r]
    float* red = Pt  + 64 * SPAD;       // [64][17]
    float* m_s = red + 64 * 17;         // [64]
    float* l_s = m_s + 64;              // [64]
    float* alf = l_s + 64;              // [64]

    const int tid = threadIdx.x;
    const int tx  = tid & 15;
    const int ty  = tid >> 4;
    const int q0  = blockIdx.x * BQ;
    const int hb  = blockIdx.y;
    const int h   = hb / BATCH;
    const int b   = hb % BATCH;

    const float* Qbase = g_q + (size_t)b * SEQ * D_MODEL + h * DKH;
    const float* Kbase = g_k + (size_t)b * SEQ * D_MODEL + h * DKH;
    const float* Vbase = g_v + (size_t)b * SEQ * D_MODEL + h * DKH;

    // load Q tile, transposed + pre-scaled by 1/sqrt(64)
#pragma unroll
    for (int it = 0; it < 4; it++) {
        int idx = tid + it * 256;
        int r   = idx >> 4;
        int dg  = (idx & 15) * 4;
        float4 v = *(const float4*)(Qbase + (size_t)(q0 + r) * D_MODEL + dg);
        Qt[(dg + 0) * SPAD + r] = v.x * 0.125f;
        Qt[(dg + 1) * SPAD + r] = v.y * 0.125f;
        Qt[(dg + 2) * SPAD + r] = v.z * 0.125f;
        Qt[(dg + 3) * SPAD + r] = v.w * 0.125f;
    }
    if (tid < 64) { m_s[tid] = -1e30f; l_s[tid] = 0.f; }

    float O[4][4];
#pragma unroll
    for (int i = 0; i < 4; i++)
#pragma unroll
        for (int j = 0; j < 4; j++) O[i][j] = 0.f;

    __syncthreads();

    for (int kt = 0; kt < SEQ; kt += BKT) {
        // ---- load K (transposed) and V (natural) ----
#pragma unroll
        for (int it = 0; it < 4; it++) {
            int idx = tid + it * 256;
            int r   = idx >> 4;
            int dg  = (idx & 15) * 4;
            float4 kv = *(const float4*)(Kbase + (size_t)(kt + r) * D_MODEL + dg);
            Kt[(dg + 0) * SPAD + r] = kv.x;
            Kt[(dg + 1) * SPAD + r] = kv.y;
            Kt[(dg + 2) * SPAD + r] = kv.z;
            Kt[(dg + 3) * SPAD + r] = kv.w;
            float4 vv = *(const float4*)(Vbase + (size_t)(kt + r) * D_MODEL + dg);
            *(float4*)&Vs[r * SPAD + dg] = vv;
        }
        __syncthreads();

        // ---- S = Qs @ K^T (scaled already) ----
        float Sa[4][4];
#pragma unroll
        for (int i = 0; i < 4; i++)
#pragma unroll
            for (int j = 0; j < 4; j++) Sa[i][j] = 0.f;

#pragma unroll 8
        for (int d = 0; d < DKH; d++) {
            float4 qf = *(const float4*)&Qt[d * SPAD + ty * 4];
            float4 kf = *(const float4*)&Kt[d * SPAD + tx * 4];
            float qa[4] = {qf.x, qf.y, qf.z, qf.w};
            float ka[4] = {kf.x, kf.y, kf.z, kf.w};
#pragma unroll
            for (int i = 0; i < 4; i++)
#pragma unroll
                for (int j = 0; j < 4; j++) Sa[i][j] += qa[i] * ka[j];
        }

        // ---- local row max ----
#pragma unroll
        for (int i = 0; i < 4; i++) {
            float mx = fmaxf(fmaxf(Sa[i][0], Sa[i][1]), fmaxf(Sa[i][2], Sa[i][3]));
            red[(ty * 4 + i) * 17 + tx] = mx;
        }
        __syncthreads();

        if (tid < 64) {
            float mx = red[tid * 17];
#pragma unroll
            for (int k = 1; k < 16; k++) mx = fmaxf(mx, red[tid * 17 + k]);
            float mo = m_s[tid];
            float mn = fmaxf(mo, mx);
            alf[tid] = __expf(mo - mn);
            m_s[tid] = mn;
        }
        __syncthreads();

        // ---- P = exp(S - m), row sums, rescale O ----
#pragma unroll
        for (int i = 0; i < 4; i++) {
            int   r  = ty * 4 + i;
            float mn = m_s[r];
            float a  = alf[r];
            float rs = 0.f;
#pragma unroll
            for (int j = 0; j < 4; j++) {
                float p = __expf(Sa[i][j] - mn);
                Pt[(tx * 4 + j) * SPAD + r] = p;
                rs += p;
                O[i][j] *= a;
            }
            red[r * 17 + tx] = rs;
        }
        __syncthreads();

        if (tid < 64) {
            float s = 0.f;
#pragma unroll
            for (int k = 0; k < 16; k++) s += red[tid * 17 + k];
            l_s[tid] = l_s[tid] * alf[tid] + s;
        }

        // ---- O += P @ V ----
#pragma unroll 8
        for (int jj = 0; jj < BKT; jj++) {
            float4 pf = *(const float4*)&Pt[jj * SPAD + ty * 4];
            float4 vf = *(const float4*)&Vs[jj * SPAD + tx * 4];
            float pa[4] = {pf.x, pf.y, pf.z, pf.w};
            float va[4] = {vf.x, vf.y, vf.z, vf.w};
#pragma unroll
            for (int i = 0; i < 4; i++)
#pragma unroll
                for (int j = 0; j < 4; j++) O[i][j] += pa[i] * va[j];
        }
        __syncthreads();
    }

    // ---- normalize + write merged layout out[b][s][h*64+d] ----
#pragma unroll
    for (int i = 0; i < 4; i++) {
        int   r    = ty * 4 + i;
        float linv = 1.0f / l_s[r];
        float4 o;
        o.x = O[i][0] * linv; o.y = O[i][1] * linv;
        o.z = O[i][2] * linv; o.w = O[i][3] * linv;
        float* Op = g_o + (size_t)(b * SEQ + q0 + r) * D_MODEL + h * DKH + tx * 4;
        *(float4*)Op = o;
    }
}

// ============================================================================
// launch — kernel launches only (plus one func-attribute set, not a stream op)
// ============================================================================
extern "C" void kernel_launch(void* const* d_in, const int* in_sizes, int n_in,
                              void* d_out, int out_size)
{
    const float* q   = (const float*)d_in[0];
    const float* k   = (const float*)d_in[1];
    const float* v   = (const float*)d_in[2];
    const float* w_q = (const float*)d_in[3];
    const float* b_q = (const float*)d_in[4];
    const float* w_k = (const float*)d_in[5];
    const float* b_k = (const float*)d_in[6];
    const float* w_v = (const float*)d_in[7];
    const float* b_v = (const float*)d_in[8];
    const float* w_o = (const float*)d_in[9];
    const float* b_o = (const float*)d_in[10];
    float* out = (float*)d_out;

    const int attn_smem = (4 * 64 * SPAD + 64 * 17 + 3 * 64) * (int)sizeof(float);
    cudaFuncSetAttribute(attn_kernel,
                         cudaFuncAttributeMaxDynamicSharedMemorySize, attn_smem);

    dim3 gemm_grid(D_MODEL / 128, MROWS / 128);   // (8, 32)
    sgemm_bias_kernel<<<gemm_grid, 256>>>(q, w_q, b_q, nullptr, 0, 0);
    sgemm_bias_kernel<<<gemm_grid, 256>>>(k, w_k, b_k, nullptr, 1, 0);
    sgemm_bias_kernel<<<gemm_grid, 256>>>(v, w_v, b_v, nullptr, 2, 0);

    dim3 attn_grid(SEQ / BQ, NHEAD * BATCH);      // (32, 32)
    attn_kernel<<<attn_grid, 256, attn_smem>>>();

    sgemm_bias_kernel<<<gemm_grid, 256>>>(nullptr, w_o, b_o, out, 3, 1);
}

// round 3
// speedup vs baseline: 2.0959x; 2.0959x over previous
#include <cuda_runtime.h>
#include <cstdint>

#define D_MODEL 1024
#define NHEAD   16
#define DKH     64
#define BATCH   2
#define SEQ     2048
#define MROWS   (BATCH*SEQ)   /* 4096 */

// ---------------- scratch (static device globals; no allocations) ----------
__device__ float g_q[(size_t)MROWS * D_MODEL];
__device__ float g_k[(size_t)MROWS * D_MODEL];
__device__ float g_v[(size_t)MROWS * D_MODEL];
__device__ float g_o[(size_t)MROWS * D_MODEL];

// ---------------- tf32 helpers --------------------------------------------
__device__ __forceinline__ uint32_t f2tf32(float x) {
    uint32_t r;
    asm("cvt.rna.tf32.f32 %0, %1;" : "=r"(r) : "f"(x));
    return r;
}

// D = A(16x8) * B(8x8) + C   (tf32 inputs, f32 accum)
// A row-major: a0=(g,tg) a1=(g+8,tg) a2=(g,tg+4) a3=(g+8,tg+4)
// B "col"    : b0=(k=tg,n=g) b1=(k=tg+4,n=g)
// C/D        : c0=(g,2tg) c1=(g,2tg+1) c2=(g+8,2tg) c3=(g+8,2tg+1)
__device__ __forceinline__ void mma_tf32(float* d,
                                         uint32_t a0, uint32_t a1, uint32_t a2, uint32_t a3,
                                         uint32_t b0, uint32_t b1) {
    asm("mma.sync.aligned.m16n8k8.row.col.f32.tf32.tf32.f32 "
        "{%0,%1,%2,%3}, {%4,%5,%6,%7}, {%8,%9}, {%0,%1,%2,%3};\n"
        : "+f"(d[0]), "+f"(d[1]), "+f"(d[2]), "+f"(d[3])
        : "r"(a0), "r"(a1), "r"(a2), "r"(a3), "r"(b0), "r"(b1));
}

// ============================================================================
// TF32 GEMM: C[4096,1024] = A[4096,1024] @ W[1024,1024] + bias
// BM=128 BN=128 BK=32, 256 threads = 8 warps (2 x 4), warp tile 64x32.
// Asm k-major [32][132] with XOR column swizzle (store & frag-load <=2-way).
// Bsm row-major [32][132].
// dst: 0->g_q 1->g_k 2->g_v 3->Cparam.  src_go: A from g_o.
// ============================================================================
__global__ __launch_bounds__(256) void gemm_tf32_kernel(
    const float* __restrict__ Aparam, const float* __restrict__ W,
    const float* __restrict__ bias, float* __restrict__ Cparam,
    int dst, int src_go)
{
    __shared__ uint32_t Asm[32][132];
    __shared__ uint32_t Bsm[32][132];

    const float* A = src_go ? g_o : Aparam;
    float* C;
    switch (dst) {
        case 0:  C = g_q; break;
        case 1:  C = g_k; break;
        case 2:  C = g_v; break;
        default: C = Cparam; break;
    }

    const int tid   = threadIdx.x;
    const int lane  = tid & 31;
    const int wid   = tid >> 5;
    const int g     = lane >> 2;
    const int tg    = lane & 3;
    const int warpM = wid >> 2;          // 0..1  -> 64 rows
    const int warpN = wid & 3;           // 0..3  -> 32 cols
    const int bM    = blockIdx.y * 128;
    const int bN    = blockIdx.x * 128;

    float acc[4][4][4];
#pragma unroll
    for (int mt = 0; mt < 4; mt++)
#pragma unroll
        for (int nt = 0; nt < 4; nt++)
#pragma unroll
            for (int i = 0; i < 4; i++) acc[mt][nt][i] = 0.f;

#pragma unroll 1
    for (int k0 = 0; k0 < D_MODEL; k0 += 32) {
        // ---- fill A tile (transpose to k-major + XOR swizzle) ----
#pragma unroll
        for (int it = 0; it < 4; it++) {
            int idx = tid + it * 256;
            int m   = idx >> 3;           // 0..127
            int kq  = idx & 7;            // k-quad 0..7
            float4 v = *(const float4*)(A + (size_t)(bM + m) * D_MODEL + k0 + 4 * kq);
            int c = m ^ (4 * kq);
            Asm[4 * kq + 0][c] = f2tf32(v.x);
            Asm[4 * kq + 1][c] = f2tf32(v.y);
            Asm[4 * kq + 2][c] = f2tf32(v.z);
            Asm[4 * kq + 3][c] = f2tf32(v.w);
        }
        // ---- fill B tile (natural row-major) ----
#pragma unroll
        for (int it = 0; it < 4; it++) {
            int idx = tid + it * 256;
            int k   = idx >> 5;           // 0..31
            int nq  = idx & 31;
            float4 v = *(const float4*)(W + (size_t)(k0 + k) * D_MODEL + bN + 4 * nq);
            uint4 u;
            u.x = f2tf32(v.x); u.y = f2tf32(v.y);
            u.z = f2tf32(v.z); u.w = f2tf32(v.w);
            *(uint4*)&Bsm[k][4 * nq] = u;
        }
        __syncthreads();

        // ---- compute ----
#pragma unroll
        for (int ks = 0; ks < 4; ks++) {
            const int p0 = 4 * ((2 * ks) & 7);
            const int p1 = 4 * ((2 * ks + 1) & 7);
            uint32_t a[4][4];
#pragma unroll
            for (int mt = 0; mt < 4; mt++) {
                int mbase = warpM * 64 + mt * 16 + g;
                a[mt][0] = Asm[8 * ks + tg][mbase ^ p0];
                a[mt][1] = Asm[8 * ks + tg][(mbase + 8) ^ p0];
                a[mt][2] = Asm[8 * ks + tg + 4][mbase ^ p1];
                a[mt][3] = Asm[8 * ks + tg + 4][(mbase + 8) ^ p1];
            }
            uint32_t b[4][2];
#pragma unroll
            for (int nt = 0; nt < 4; nt++) {
                int n = warpN * 32 + nt * 8 + g;
                b[nt][0] = Bsm[8 * ks + tg][n];
                b[nt][1] = Bsm[8 * ks + tg + 4][n];
            }
#pragma unroll
            for (int mt = 0; mt < 4; mt++)
#pragma unroll
                for (int nt = 0; nt < 4; nt++)
                    mma_tf32(acc[mt][nt], a[mt][0], a[mt][1], a[mt][2], a[mt][3],
                             b[nt][0], b[nt][1]);
        }
        __syncthreads();
    }

    // ---- epilogue: bias + store ----
#pragma unroll
    for (int nt = 0; nt < 4; nt++) {
        int col = bN + warpN * 32 + nt * 8 + 2 * tg;
        float2 bv = *(const float2*)&bias[col];
#pragma unroll
        for (int mt = 0; mt < 4; mt++) {
            int row = bM + warpM * 64 + mt * 16 + g;
            float2 v0, v1;
            v0.x = acc[mt][nt][0] + bv.x; v0.y = acc[mt][nt][1] + bv.y;
            v1.x = acc[mt][nt][2] + bv.x; v1.y = acc[mt][nt][3] + bv.y;
            *(float2*)&C[(size_t)row * D_MODEL + col]       = v0;
            *(float2*)&C[(size_t)(row + 8) * D_MODEL + col] = v1;
        }
    }
}

// ============================================================================
// TF32 flash attention. Block = (q-tile 64 rows, head-batch). 256 thr, 8 warps.
// Warp w: mb = w&3 (16-row m-block), nh = w>>2 (32-col n-half).
// Qs/Ks/Vs/Ps: [64][68] tf32 in smem (frag LDS <= 2-way). Online softmax fp32.
// ============================================================================
#define SSTR 68

__global__ __launch_bounds__(256) void attn_tf32_kernel()
{
    extern __shared__ uint32_t smx[];
    uint32_t* Qs = smx;                    // [64][68]
    uint32_t* Ks = Qs + 64 * SSTR;
    uint32_t* Vs = Ks + 64 * SSTR;
    uint32_t* Ps = Vs + 64 * SSTR;
    float* red_max = (float*)(Ps + 64 * SSTR);  // [2][64]
    float* red_sum = red_max + 128;             // [2][64]
    float* m_s = red_sum + 128;                 // [64]
    float* l_s = m_s + 64;                      // [64]
    float* alf = l_s + 64;                      // [64]

    const int tid  = threadIdx.x;
    const int lane = tid & 31;
    const int wid  = tid >> 5;
    const int g    = lane >> 2;
    const int tg   = lane & 3;
    const int mb   = wid & 3;
    const int nh   = wid >> 2;       // 0..1
    const int r1   = 16 * mb + g;
    const int r2   = r1 + 8;

    const int q0 = blockIdx.x * 64;
    const int hb = blockIdx.y;
    const int h  = hb / BATCH;
    const int b  = hb % BATCH;

    const float* Qbase = g_q + ((size_t)b * SEQ + q0) * D_MODEL + h * DKH;
    const float* Kbase = g_k + (size_t)b * SEQ * D_MODEL + h * DKH;
    const float* Vbase = g_v + (size_t)b * SEQ * D_MODEL + h * DKH;

    // ---- load Q tile (tf32, pre-scaled by 1/8) ----
#pragma unroll
    for (int it = 0; it < 4; it++) {
        int idx = tid + it * 256;
        int r   = idx >> 4;
        int dq  = idx & 15;
        float4 v = *(const float4*)(Qbase + (size_t)r * D_MODEL + 4 * dq);
        uint4 u;
        u.x = f2tf32(v.x * 0.125f); u.y = f2tf32(v.y * 0.125f);
        u.z = f2tf32(v.z * 0.125f); u.w = f2tf32(v.w * 0.125f);
        *(uint4*)&Qs[r * SSTR + 4 * dq] = u;
    }
    if (tid < 64) { m_s[tid] = -1e30f; l_s[tid] = 0.f; }

    float O[4][4];
#pragma unroll
    for (int nt = 0; nt < 4; nt++)
#pragma unroll
        for (int i = 0; i < 4; i++) O[nt][i] = 0.f;

    __syncthreads();

#pragma unroll 1
    for (int kt = 0; kt < SEQ; kt += 64) {
        // ---- load K, V tiles (tf32) ----
#pragma unroll
        for (int it = 0; it < 4; it++) {
            int idx = tid + it * 256;
            int r   = idx >> 4;
            int dq  = idx & 15;
            float4 kv = *(const float4*)(Kbase + (size_t)(kt + r) * D_MODEL + 4 * dq);
            uint4 ku;
            ku.x = f2tf32(kv.x); ku.y = f2tf32(kv.y);
            ku.z = f2tf32(kv.z); ku.w = f2tf32(kv.w);
            *(uint4*)&Ks[r * SSTR + 4 * dq] = ku;
            float4 vv = *(const float4*)(Vbase + (size_t)(kt + r) * D_MODEL + 4 * dq);
            uint4 vu;
            vu.x = f2tf32(vv.x); vu.y = f2tf32(vv.y);
            vu.z = f2tf32(vv.z); vu.w = f2tf32(vv.w);
            *(uint4*)&Vs[r * SSTR + 4 * dq] = vu;
        }
        __syncthreads();

        // ---- S = Q K^T (warp tile 16 x 32) ----
        float S[4][4];
#pragma unroll
        for (int nt = 0; nt < 4; nt++)
#pragma unroll
            for (int i = 0; i < 4; i++) S[nt][i] = 0.f;

#pragma unroll
        for (int ks = 0; ks < 8; ks++) {
            uint32_t a0 = Qs[r1 * SSTR + 8 * ks + tg];
            uint32_t a1 = Qs[r2 * SSTR + 8 * ks + tg];
            uint32_t a2 = Qs[r1 * SSTR + 8 * ks + tg + 4];
            uint32_t a3 = Qs[r2 * SSTR + 8 * ks + tg + 4];
#pragma unroll
            for (int nt = 0; nt < 4; nt++) {
                int n = 32 * nh + 8 * nt + g;
                uint32_t b0 = Ks[n * SSTR + 8 * ks + tg];
                uint32_t b1 = Ks[n * SSTR + 8 * ks + tg + 4];
                mma_tf32(S[nt], a0, a1, a2, a3, b0, b1);
            }
        }

        // ---- row max (this tile, this n-half) ----
        float mx1 = -1e30f, mx2 = -1e30f;
#pragma unroll
        for (int nt = 0; nt < 4; nt++) {
            mx1 = fmaxf(mx1, fmaxf(S[nt][0], S[nt][1]));
            mx2 = fmaxf(mx2, fmaxf(S[nt][2], S[nt][3]));
        }
        mx1 = fmaxf(mx1, __shfl_xor_sync(0xffffffffu, mx1, 1));
        mx1 = fmaxf(mx1, __shfl_xor_sync(0xffffffffu, mx1, 2));
        mx2 = fmaxf(mx2, __shfl_xor_sync(0xffffffffu, mx2, 1));
        mx2 = fmaxf(mx2, __shfl_xor_sync(0xffffffffu, mx2, 2));
        red_max[nh * 64 + r1] = mx1;
        red_max[nh * 64 + r2] = mx2;
        __syncthreads();

        if (tid < 64) {
            float mt = fmaxf(red_max[tid], red_max[64 + tid]);
            float mo = m_s[tid];
            float mn = fmaxf(mo, mt);
            alf[tid] = __expf(mo - mn);
            m_s[tid] = mn;
        }
        __syncthreads();

        // ---- P = exp(S - m), rescale O, row sums, store P (tf32) ----
        const float mn1 = m_s[r1], mn2 = m_s[r2];
        const float a1v = alf[r1], a2v = alf[r2];
        float sum1 = 0.f, sum2 = 0.f;
#pragma unroll
        for (int nt = 0; nt < 4; nt++) {
            float p0 = __expf(S[nt][0] - mn1);
            float p1 = __expf(S[nt][1] - mn1);
            float p2 = __expf(S[nt][2] - mn2);
            float p3 = __expf(S[nt][3] - mn2);
            sum1 += p0 + p1;
            sum2 += p2 + p3;
            O[nt][0] *= a1v; O[nt][1] *= a1v;
            O[nt][2] *= a2v; O[nt][3] *= a2v;
            int c = 32 * nh + 8 * nt + 2 * tg;
            uint2 u1; u1.x = f2tf32(p0); u1.y = f2tf32(p1);
            uint2 u2; u2.x = f2tf32(p2); u2.y = f2tf32(p3);
            *(uint2*)&Ps[r1 * SSTR + c] = u1;
            *(uint2*)&Ps[r2 * SSTR + c] = u2;
        }
        sum1 += __shfl_xor_sync(0xffffffffu, sum1, 1);
        sum1 += __shfl_xor_sync(0xffffffffu, sum1, 2);
        sum2 += __shfl_xor_sync(0xffffffffu, sum2, 1);
        sum2 += __shfl_xor_sync(0xffffffffu, sum2, 2);
        red_sum[nh * 64 + r1] = sum1;
        red_sum[nh * 64 + r2] = sum2;
        __syncthreads();

        if (tid < 64)
            l_s[tid] = l_s[tid] * alf[tid] + red_sum[tid] + red_sum[64 + tid];

        // ---- O += P V ----
#pragma unroll
        for (int ks = 0; ks < 8; ks++) {
            uint32_t a0 = Ps[r1 * SSTR + 8 * ks + tg];
            uint32_t a1 = Ps[r2 * SSTR + 8 * ks + tg];
            uint32_t a2 = Ps[r1 * SSTR + 8 * ks + tg + 4];
            uint32_t a3 = Ps[r2 * SSTR + 8 * ks + tg + 4];
#pragma unroll
            for (int nt = 0; nt < 4; nt++) {
                int n = 32 * nh + 8 * nt + g;
                uint32_t b0 = Vs[(8 * ks + tg) * SSTR + n];
                uint32_t b1 = Vs[(8 * ks + tg + 4) * SSTR + n];
                mma_tf32(O[nt], a0, a1, a2, a3, b0, b1);
            }
        }
        __syncthreads();
    }

    // ---- normalize + write merged layout out[b][s][h*64 + d] ----
    const float li1 = 1.0f / l_s[r1];
    const float li2 = 1.0f / l_s[r2];
#pragma unroll
    for (int nt = 0; nt < 4; nt++) {
        int c = 32 * nh + 8 * nt + 2 * tg;
        float2 v1, v2;
        v1.x = O[nt][0] * li1; v1.y = O[nt][1] * li1;
        v2.x = O[nt][2] * li2; v2.y = O[nt][3] * li2;
        *(float2*)&g_o[((size_t)b * SEQ + q0 + r1) * D_MODEL + h * DKH + c] = v1;
        *(float2*)&g_o[((size_t)b * SEQ + q0 + r2) * D_MODEL + h * DKH + c] = v2;
    }
}

// ============================================================================
// launch — kernel launches only
// ============================================================================
extern "C" void kernel_launch(void* const* d_in, const int* in_sizes, int n_in,
                              void* d_out, int out_size)
{
    const float* q   = (const float*)d_in[0];
    const float* k   = (const float*)d_in[1];
    const float* v   = (const float*)d_in[2];
    const float* w_q = (const float*)d_in[3];
    const float* b_q = (const float*)d_in[4];
    const float* w_k = (const float*)d_in[5];
    const float* b_k = (const float*)d_in[6];
    const float* w_v = (const float*)d_in[7];
    const float* b_v = (const float*)d_in[8];
    const float* w_o = (const float*)d_in[9];
    const float* b_o = (const float*)d_in[10];
    float* out = (float*)d_out;

    const int attn_smem = (4 * 64 * SSTR + 128 + 128 + 3 * 64) * (int)sizeof(uint32_t);
    cudaFuncSetAttribute(attn_tf32_kernel,
                         cudaFuncAttributeMaxDynamicSharedMemorySize, attn_smem);

    dim3 gemm_grid(D_MODEL / 128, MROWS / 128);   // (8, 32)
    gemm_tf32_kernel<<<gemm_grid, 256>>>(q, w_q, b_q, nullptr, 0, 0);
    gemm_tf32_kernel<<<gemm_grid, 256>>>(k, w_k, b_k, nullptr, 1, 0);
    gemm_tf32_kernel<<<gemm_grid, 256>>>(v, w_v, b_v, nullptr, 2, 0);

    dim3 attn_grid(SEQ / 64, NHEAD * BATCH);      // (32, 32)
    attn_tf32_kernel<<<attn_grid, 256, attn_smem>>>();

    gemm_tf32_kernel<<<gemm_grid, 256>>>(nullptr, w_o, b_o, out, 3, 1);
}

// round 4
// speedup vs baseline: 3.3398x; 1.5935x over previous
#include <cuda_runtime.h>
#include <cstdint>

#define D_MODEL 1024
#define NHEAD   16
#define DKH     64
#define BATCH   2
#define SEQ     2048
#define MROWS   (BATCH*SEQ)   /* 4096 */

// ---------------- scratch (static device globals; no allocations) ----------
__device__ float g_q [(size_t)MROWS * D_MODEL];   // proj outputs (tf32-rounded)
__device__ float g_k [(size_t)MROWS * D_MODEL];
__device__ float g_v [(size_t)MROWS * D_MODEL];
__device__ float g_o [(size_t)MROWS * D_MODEL];   // attn out (tf32-rounded)
__device__ float g_qc[(size_t)MROWS * D_MODEL];   // tf32-rounded inputs
__device__ float g_kc[(size_t)MROWS * D_MODEL];
__device__ float g_vc[(size_t)MROWS * D_MODEL];
__device__ float g_wq[(size_t)D_MODEL * D_MODEL];
__device__ float g_wk[(size_t)D_MODEL * D_MODEL];
__device__ float g_wv[(size_t)D_MODEL * D_MODEL];
__device__ float g_wo[(size_t)D_MODEL * D_MODEL];

// ---------------- helpers ---------------------------------------------------
__device__ __forceinline__ uint32_t f2tf32(float x) {
    uint32_t r;
    asm("cvt.rna.tf32.f32 %0, %1;" : "=r"(r) : "f"(x));
    return r;
}
__device__ __forceinline__ float tf32r(float x) { return __uint_as_float(f2tf32(x)); }

__device__ __forceinline__ uint32_t smem_u32(const void* p) {
    return (uint32_t)__cvta_generic_to_shared(p);
}
__device__ __forceinline__ void cpa16(uint32_t dst, const void* src) {
    asm volatile("cp.async.cg.shared.global [%0], [%1], 16;\n" :: "r"(dst), "l"(src));
}
#define CPA_COMMIT() asm volatile("cp.async.commit_group;\n" ::: "memory")
#define CPA_WAIT(n)  asm volatile("cp.async.wait_group %0;\n" :: "n"(n) : "memory")

// D(16x8) += A(16x8) * B(8x8), tf32 in, f32 accum.
__device__ __forceinline__ void mma_tf32(float* d,
                                         uint32_t a0, uint32_t a1, uint32_t a2, uint32_t a3,
                                         uint32_t b0, uint32_t b1) {
    asm("mma.sync.aligned.m16n8k8.row.col.f32.tf32.tf32.f32 "
        "{%0,%1,%2,%3}, {%4,%5,%6,%7}, {%8,%9}, {%0,%1,%2,%3};\n"
        : "+f"(d[0]), "+f"(d[1]), "+f"(d[2]), "+f"(d[3])
        : "r"(a0), "r"(a1), "r"(a2), "r"(a3), "r"(b0), "r"(b1));
}

// ============================================================================
// Preconvert: tf32-round q,k,v,w_* into scratch (z = tensor id 0..6).
// ============================================================================
__global__ __launch_bounds__(256) void preconv_kernel(
    const float* __restrict__ q, const float* __restrict__ k, const float* __restrict__ v,
    const float* __restrict__ wq, const float* __restrict__ wk,
    const float* __restrict__ wv, const float* __restrict__ wo)
{
    const float* src; float* dst; int n4;
    switch (blockIdx.z) {
        case 0: src = q;  dst = g_qc; n4 = MROWS * D_MODEL / 4; break;
        case 1: src = k;  dst = g_kc; n4 = MROWS * D_MODEL / 4; break;
        case 2: src = v;  dst = g_vc; n4 = MROWS * D_MODEL / 4; break;
        case 3: src = wq; dst = g_wq; n4 = D_MODEL * D_MODEL / 4; break;
        case 4: src = wk; dst = g_wk; n4 = D_MODEL * D_MODEL / 4; break;
        case 5: src = wv; dst = g_wv; n4 = D_MODEL * D_MODEL / 4; break;
        default: src = wo; dst = g_wo; n4 = D_MODEL * D_MODEL / 4; break;
    }
    int idx = blockIdx.x * 256 + threadIdx.x;
    if (idx < n4) {
        float4 t = ((const float4*)src)[idx];
        t.x = tf32r(t.x); t.y = tf32r(t.y); t.z = tf32r(t.z); t.w = tf32r(t.w);
        ((float4*)dst)[idx] = t;
    }
}

// ============================================================================
// TF32 GEMM, all operands pre-rounded. 3-stage cp.async pipeline.
// BM=BN=128, BK=32. 256 thr, warp tile 64x32.  A smem [128][36], B smem [32][136].
// mode 0: z=0..2 -> qc/kc/vc @ wq/wk/wv -> g_q/g_k/g_v (write tf32-rounded).
// mode 1: g_o @ wo -> Cout (raw fp32).
// ============================================================================
#define ASTR 36
#define BSTR 136
#define ASTG (128*ASTR)
#define BSTG (32*BSTR)
#define GEMM_SMEM_BYTES (3*(ASTG+BSTG)*4)

__global__ __launch_bounds__(256, 2) void gemm_kernel(
    const float* __restrict__ bq, const float* __restrict__ bk,
    const float* __restrict__ bv, const float* __restrict__ bo,
    float* __restrict__ Cout, int mode)
{
    extern __shared__ float smg[];
    uint32_t sA = smem_u32(smg);                  // bytes
    uint32_t sB = sA + 3 * ASTG * 4;

    int zz = mode ? 3 : blockIdx.z;
    const float *A, *W, *bias; float* C;
    switch (zz) {
        case 0:  A = g_qc; W = g_wq; bias = bq; C = g_q;  break;
        case 1:  A = g_kc; W = g_wk; bias = bk; C = g_k;  break;
        case 2:  A = g_vc; W = g_wv; bias = bv; C = g_v;  break;
        default: A = g_o;  W = g_wo; bias = bo; C = Cout; break;
    }
    const bool rnd = (zz < 3);

    const int tid   = threadIdx.x;
    const int lane  = tid & 31;
    const int wid   = tid >> 5;
    const int g     = lane >> 2;
    const int tg    = lane & 3;
    const int warpM = wid >> 2;
    const int warpN = wid & 3;
    const int bM    = blockIdx.y * 128;
    const int bN    = blockIdx.x * 128;

    // per-thread copy coords
    const int am = tid >> 3, akq = tid & 7;        // A: 4 chunks, rows am+32*it
    const int bk_ = tid >> 5, bnq = tid & 31;      // B: 4 chunks, k rows bk_+8*it
    const float* Ab = A + (size_t)(bM + am) * D_MODEL + akq * 4;
    const float* Wb = W + (size_t)bk_ * D_MODEL + bN + bnq * 4;
    const uint32_t aOff = (uint32_t)(am * ASTR + akq * 4) * 4;
    const uint32_t bOff = (uint32_t)(bk_ * BSTR + bnq * 4) * 4;

#define GEMM_ISSUE(kt, st)                                                      \
    do {                                                                        \
        uint32_t as_ = sA + (uint32_t)(st) * ASTG * 4 + aOff;                   \
        uint32_t bs_ = sB + (uint32_t)(st) * BSTG * 4 + bOff;                   \
        _Pragma("unroll")                                                       \
        for (int it = 0; it < 4; it++)                                          \
            cpa16(as_ + it * 32 * ASTR * 4, Ab + (size_t)it * 32 * D_MODEL + (kt) * 32); \
        _Pragma("unroll")                                                       \
        for (int it = 0; it < 4; it++)                                          \
            cpa16(bs_ + it * 8 * BSTR * 4, Wb + (size_t)((kt) * 32 + it * 8) * D_MODEL); \
    } while (0)

    float acc[4][4][4];
#pragma unroll
    for (int mt = 0; mt < 4; mt++)
#pragma unroll
        for (int nt = 0; nt < 4; nt++)
#pragma unroll
            for (int i = 0; i < 4; i++) acc[mt][nt][i] = 0.f;

    GEMM_ISSUE(0, 0); CPA_COMMIT();
    GEMM_ISSUE(1, 1); CPA_COMMIT();

    const uint32_t* Asu = (const uint32_t*)smg;
    const uint32_t* Bsu = (const uint32_t*)(smg + 3 * ASTG);

#pragma unroll 1
    for (int kt = 0; kt < 32; kt++) {
        CPA_WAIT(1);
        __syncthreads();
        if (kt + 2 < 32) GEMM_ISSUE(kt + 2, (kt + 2) % 3);
        CPA_COMMIT();

        const uint32_t* Ast = Asu + (kt % 3) * ASTG;
        const uint32_t* Bst = Bsu + (kt % 3) * BSTG;
#pragma unroll
        for (int ks = 0; ks < 4; ks++) {
            uint32_t a[4][4];
#pragma unroll
            for (int mt = 0; mt < 4; mt++) {
                int r = warpM * 64 + mt * 16 + g;
                a[mt][0] = Ast[r * ASTR + 8 * ks + tg];
                a[mt][1] = Ast[(r + 8) * ASTR + 8 * ks + tg];
                a[mt][2] = Ast[r * ASTR + 8 * ks + tg + 4];
                a[mt][3] = Ast[(r + 8) * ASTR + 8 * ks + tg + 4];
            }
            uint32_t b[4][2];
#pragma unroll
            for (int nt = 0; nt < 4; nt++) {
                int n = warpN * 32 + nt * 8 + g;
                b[nt][0] = Bst[(8 * ks + tg) * BSTR + n];
                b[nt][1] = Bst[(8 * ks + tg + 4) * BSTR + n];
            }
#pragma unroll
            for (int mt = 0; mt < 4; mt++)
#pragma unroll
                for (int nt = 0; nt < 4; nt++)
                    mma_tf32(acc[mt][nt], a[mt][0], a[mt][1], a[mt][2], a[mt][3],
                             b[nt][0], b[nt][1]);
        }
    }

    // epilogue
#pragma unroll
    for (int nt = 0; nt < 4; nt++) {
        int col = bN + warpN * 32 + nt * 8 + 2 * tg;
        float2 bv2 = *(const float2*)&bias[col];
#pragma unroll
        for (int mt = 0; mt < 4; mt++) {
            int row = bM + warpM * 64 + mt * 16 + g;
            float2 v0, v1;
            v0.x = acc[mt][nt][0] + bv2.x; v0.y = acc[mt][nt][1] + bv2.y;
            v1.x = acc[mt][nt][2] + bv2.x; v1.y = acc[mt][nt][3] + bv2.y;
            if (rnd) {
                v0.x = tf32r(v0.x); v0.y = tf32r(v0.y);
                v1.x = tf32r(v1.x); v1.y = tf32r(v1.y);
            }
            *(float2*)&C[(size_t)row * D_MODEL + col]       = v0;
            *(float2*)&C[(size_t)(row + 8) * D_MODEL + col] = v1;
        }
    }
#undef GEMM_ISSUE
}

// ============================================================================
// TF32 flash attention. BQ=128, BKT=64. 8 warps: mg=wid>>1 (32 rows), nh=wid&1.
// Warp tile 32x32 (2 m-blocks x 4 n-blocks). Inputs pre-rounded; Q-scale folded
// into S (*0.125 exact). K(t+1) prefetch overlaps softmax+PV. smem ~109KB.
// ============================================================================
#define QSTR 68
#define KSTR 68
#define VSTR 72
#define PSTR 68
#define ATT_WORDS (128*QSTR + 64*KSTR + 64*VSTR + 128*PSTR + 256 + 256 + 3*128)
#define ATT_SMEM_BYTES (ATT_WORDS * 4)

__global__ __launch_bounds__(256, 2) void attn_kernel()
{
    extern __shared__ float sma[];
    float*    Qs  = sma;
    float*    Ks  = Qs  + 128 * QSTR;
    float*    Vs  = Ks  + 64 * KSTR;
    float*    Ps  = Vs  + 64 * VSTR;
    float* red_mx = Ps  + 128 * PSTR;   // [2][128]
    float* red_sm = red_mx + 256;       // [2][128]
    float* m_s    = red_sm + 256;       // [128]
    float* l_s    = m_s + 128;
    float* alf    = l_s + 128;

    const uint32_t sQ = smem_u32(Qs), sK = smem_u32(Ks), sV = smem_u32(Vs);
    const uint32_t* Qu = (const uint32_t*)Qs;
    const uint32_t* Ku = (const uint32_t*)Ks;
    const uint32_t* Vu = (const uint32_t*)Vs;
    uint32_t*       Pu = (uint32_t*)Ps;

    const int tid  = threadIdx.x;
    const int lane = tid & 31;
    const int wid  = tid >> 5;
    const int g    = lane >> 2;
    const int tg   = lane & 3;
    const int mg   = wid >> 1;
    const int nh   = wid & 1;
    const int rA0  = 32 * mg + g;        // mt=0 rows: rA0, rA0+8; mt=1: +16
    const int q0   = blockIdx.x * 128;
    const int hb   = blockIdx.y;
    const int h    = hb / BATCH;
    const int b    = hb % BATCH;

    const float* Qb = g_q + ((size_t)b * SEQ + q0) * D_MODEL + h * DKH;
    const float* Kb = g_k + (size_t)b * SEQ * D_MODEL + h * DKH;
    const float* Vb = g_v + (size_t)b * SEQ * D_MODEL + h * DKH;

    // copy coords: row = idx>>4, dq = idx&15 (16B chunks over 64 cols)
    const int crow = tid >> 4, cdq = tid & 15;

    // prologue: Q (8 chunks), K/V tile 0 (4 chunks each)
#pragma unroll
    for (int it = 0; it < 8; it++)
        cpa16(sQ + (uint32_t)((crow + it * 16) * QSTR + cdq * 4) * 4,
              Qb + (size_t)(crow + it * 16) * D_MODEL + cdq * 4);
#pragma unroll
    for (int it = 0; it < 4; it++)
        cpa16(sK + (uint32_t)((crow + it * 16) * KSTR + cdq * 4) * 4,
              Kb + (size_t)(crow + it * 16) * D_MODEL + cdq * 4);
#pragma unroll
    for (int it = 0; it < 4; it++)
        cpa16(sV + (uint32_t)((crow + it * 16) * VSTR + cdq * 4) * 4,
              Vb + (size_t)(crow + it * 16) * D_MODEL + cdq * 4);
    CPA_COMMIT();

    if (tid < 128) { m_s[tid] = -1e30f; l_s[tid] = 0.f; }

    float O[2][4][4];
#pragma unroll
    for (int mt = 0; mt < 2; mt++)
#pragma unroll
        for (int nt = 0; nt < 4; nt++)
#pragma unroll
            for (int i = 0; i < 4; i++) O[mt][nt][i] = 0.f;

#pragma unroll 1
    for (int kt = 0; kt < SEQ / 64; kt++) {
        CPA_WAIT(0);
        __syncthreads();                                   // S1: K/V(t), init ready

        // ---- S = Q K^T ----
        float S[2][4][4];
#pragma unroll
        for (int mt = 0; mt < 2; mt++)
#pragma unroll
            for (int nt = 0; nt < 4; nt++)
#pragma unroll
                for (int i = 0; i < 4; i++) S[mt][nt][i] = 0.f;

#pragma unroll
        for (int ks = 0; ks < 8; ks++) {
            uint32_t a[2][4];
#pragma unroll
            for (int mt = 0; mt < 2; mt++) {
                int r = rA0 + 16 * mt;
                a[mt][0] = Qu[r * QSTR + 8 * ks + tg];
                a[mt][1] = Qu[(r + 8) * QSTR + 8 * ks + tg];
                a[mt][2] = Qu[r * QSTR + 8 * ks + tg + 4];
                a[mt][3] = Qu[(r + 8) * QSTR + 8 * ks + tg + 4];
            }
#pragma unroll
            for (int nt = 0; nt < 4; nt++) {
                int n = 32 * nh + 8 * nt + g;
                uint32_t b0 = Ku[n * KSTR + 8 * ks + tg];
                uint32_t b1 = Ku[n * KSTR + 8 * ks + tg + 4];
                mma_tf32(S[0][nt], a[0][0], a[0][1], a[0][2], a[0][3], b0, b1);
                mma_tf32(S[1][nt], a[1][0], a[1][1], a[1][2], a[1][3], b0, b1);
            }
        }
#pragma unroll
        for (int mt = 0; mt < 2; mt++)
#pragma unroll
            for (int nt = 0; nt < 4; nt++)
#pragma unroll
                for (int i = 0; i < 4; i++) S[mt][nt][i] *= 0.125f;

        // ---- row max ----
#pragma unroll
        for (int mt = 0; mt < 2; mt++) {
            float mxA = -1e30f, mxB = -1e30f;
#pragma unroll
            for (int nt = 0; nt < 4; nt++) {
                mxA = fmaxf(mxA, fmaxf(S[mt][nt][0], S[mt][nt][1]));
                mxB = fmaxf(mxB, fmaxf(S[mt][nt][2], S[mt][nt][3]));
            }
            mxA = fmaxf(mxA, __shfl_xor_sync(0xffffffffu, mxA, 1));
            mxA = fmaxf(mxA, __shfl_xor_sync(0xffffffffu, mxA, 2));
            mxB = fmaxf(mxB, __shfl_xor_sync(0xffffffffu, mxB, 1));
            mxB = fmaxf(mxB, __shfl_xor_sync(0xffffffffu, mxB, 2));
            if (tg == 0) {
                red_mx[nh * 128 + rA0 + 16 * mt]     = mxA;
                red_mx[nh * 128 + rA0 + 16 * mt + 8] = mxB;
            }
        }
        __syncthreads();                                   // S2: QK done everywhere

        // prefetch K(t+1) — Ks free now
        if (kt + 1 < SEQ / 64) {
#pragma unroll
            for (int it = 0; it < 4; it++)
                cpa16(sK + (uint32_t)((crow + it * 16) * KSTR + cdq * 4) * 4,
                      Kb + (size_t)((kt + 1) * 64 + crow + it * 16) * D_MODEL + cdq * 4);
        }

        if (tid < 128) {
            float mt_ = fmaxf(red_mx[tid], red_mx[128 + tid]);
            float mo  = m_s[tid];
            float mn  = fmaxf(mo, mt_);
            alf[tid] = __expf(mo - mn);
            m_s[tid] = mn;
        }
        __syncthreads();                                   // S3: m/alf ready

        // ---- P = exp(S-m), rescale O, row sums, store P ----
#pragma unroll
        for (int mt = 0; mt < 2; mt++) {
            int rA = rA0 + 16 * mt, rB = rA + 8;
            float mnA = m_s[rA], mnB = m_s[rB];
            float aA = alf[rA], aB = alf[rB];
            float sA = 0.f, sB = 0.f;
#pragma unroll
            for (int nt = 0; nt < 4; nt++) {
                float p0 = __expf(S[mt][nt][0] - mnA);
                float p1 = __expf(S[mt][nt][1] - mnA);
                float p2 = __expf(S[mt][nt][2] - mnB);
                float p3 = __expf(S[mt][nt][3] - mnB);
                sA += p0 + p1; sB += p2 + p3;
                O[mt][nt][0] *= aA; O[mt][nt][1] *= aA;
                O[mt][nt][2] *= aB; O[mt][nt][3] *= aB;
                int c = 32 * nh + 8 * nt + 2 * tg;
                uint2 uA; uA.x = f2tf32(p0); uA.y = f2tf32(p1);
                uint2 uB; uB.x = f2tf32(p2); uB.y = f2tf32(p3);
                *(uint2*)&Pu[rA * PSTR + c] = uA;
                *(uint2*)&Pu[rB * PSTR + c] = uB;
            }
            sA += __shfl_xor_sync(0xffffffffu, sA, 1);
            sA += __shfl_xor_sync(0xffffffffu, sA, 2);
            sB += __shfl_xor_sync(0xffffffffu, sB, 1);
            sB += __shfl_xor_sync(0xffffffffu, sB, 2);
            if (tg == 0) {
                red_sm[nh * 128 + rA] = sA;
                red_sm[nh * 128 + rB] = sB;
            }
        }
        __syncthreads();                                   // S4: P visible

        if (tid < 128)
            l_s[tid] = l_s[tid] * alf[tid] + red_sm[tid] + red_sm[128 + tid];

        // ---- O += P V ----
#pragma unroll
        for (int ks = 0; ks < 8; ks++) {
            uint32_t a[2][4];
#pragma unroll
            for (int mt = 0; mt < 2; mt++) {
                int r = rA0 + 16 * mt;
                a[mt][0] = Pu[r * PSTR + 8 * ks + tg];
                a[mt][1] = Pu[(r + 8) * PSTR + 8 * ks + tg];
                a[mt][2] = Pu[r * PSTR + 8 * ks + tg + 4];
                a[mt][3] = Pu[(r + 8) * PSTR + 8 * ks + tg + 4];
            }
#pragma unroll
            for (int nt = 0; nt < 4; nt++) {
                int n = 32 * nh + 8 * nt + g;
                uint32_t b0 = Vu[(8 * ks + tg) * VSTR + n];
                uint32_t b1 = Vu[(8 * ks + tg + 4) * VSTR + n];
                mma_tf32(O[0][nt], a[0][0], a[0][1], a[0][2], a[0][3], b0, b1);
                mma_tf32(O[1][nt], a[1][0], a[1][1], a[1][2], a[1][3], b0, b1);
            }
        }
        __syncthreads();                                   // S5: Vs free

        if (kt + 1 < SEQ / 64) {
#pragma unroll
            for (int it = 0; it < 4; it++)
                cpa16(sV + (uint32_t)((crow + it * 16) * VSTR + cdq * 4) * 4,
                      Vb + (size_t)((kt + 1) * 64 + crow + it * 16) * D_MODEL + cdq * 4);
        }
        CPA_COMMIT();
    }

    // ---- epilogue: normalize, tf32-round, write merged layout ----
#pragma unroll
    for (int mt = 0; mt < 2; mt++) {
        int rA = rA0 + 16 * mt, rB = rA + 8;
        float liA = 1.0f / l_s[rA];
        float liB = 1.0f / l_s[rB];
#pragma unroll
        for (int nt = 0; nt < 4; nt++) {
            int c = 32 * nh + 8 * nt + 2 * tg;
            float2 vA, vB;
            vA.x = tf32r(O[mt][nt][0] * liA); vA.y = tf32r(O[mt][nt][1] * liA);
            vB.x = tf32r(O[mt][nt][2] * liB); vB.y = tf32r(O[mt][nt][3] * liB);
            *(float2*)&g_o[((size_t)b * SEQ + q0 + rA) * D_MODEL + h * DKH + c] = vA;
            *(float2*)&g_o[((size_t)b * SEQ + q0 + rB) * D_MODEL + h * DKH + c] = vB;
        }
    }
}

// ============================================================================
// launch
// ============================================================================
extern "C" void kernel_launch(void* const* d_in, const int* in_sizes, int n_in,
                              void* d_out, int out_size)
{
    const float* q   = (const float*)d_in[0];
    const float* k   = (const float*)d_in[1];
    const float* v   = (const float*)d_in[2];
    const float* w_q = (const float*)d_in[3];
    const float* b_q = (const float*)d_in[4];
    const float* w_k = (const float*)d_in[5];
    const float* b_k = (const float*)d_in[6];
    const float* w_v = (const float*)d_in[7];
    const float* b_v = (const float*)d_in[8];
    const float* w_o = (const float*)d_in[9];
    const float* b_o = (const float*)d_in[10];
    float* out = (float*)d_out;

    cudaFuncSetAttribute(gemm_kernel,
                         cudaFuncAttributeMaxDynamicSharedMemorySize, GEMM_SMEM_BYTES);
    cudaFuncSetAttribute(attn_kernel,
                         cudaFuncAttributeMaxDynamicSharedMemorySize, ATT_SMEM_BYTES);

    dim3 cvt_grid(MROWS * D_MODEL / 4 / 256, 1, 7);
    preconv_kernel<<<cvt_grid, 256>>>(q, k, v, w_q, w_k, w_v, w_o);

    dim3 qkv_grid(D_MODEL / 128, MROWS / 128, 3);
    gemm_kernel<<<qkv_grid, 256, GEMM_SMEM_BYTES>>>(b_q, b_k, b_v, b_o, nullptr, 0);

    dim3 attn_grid(SEQ / 128, NHEAD * BATCH);
    attn_kernel<<<attn_grid, 256, ATT_SMEM_BYTES>>>();

    dim3 o_grid(D_MODEL / 128, MROWS / 128, 1);
    gemm_kernel<<<o_grid, 256, GEMM_SMEM_BYTES>>>(b_q, b_k, b_v, b_o, out, 1);
}